// round 2
// baseline (speedup 1.0000x reference)
#include <cuda_runtime.h>
#include <cuda_bf16.h>

#define ZD 21
#define YD 256
#define XD 256
#define CIN 16
#define C1 32
#define C2 64
#define BN_EPS 1e-3f
#define GRID_SZ (2 * ZD * YD * XD)   // 2,752,512
#define NMAX 400000

// Scratch (allocs are forbidden; __device__ globals are the sanctioned path)
__device__ int   g_grid[GRID_SZ];
__device__ float g_f1[NMAX * C1];

// ---------------------------------------------------------------------------
// Hash-grid build
// ---------------------------------------------------------------------------
__global__ void fill_grid_kernel() {
    int i = blockIdx.x * blockDim.x + threadIdx.x;
    if (i < GRID_SZ / 4) {
        ((int4*)g_grid)[i] = make_int4(-1, -1, -1, -1);
    }
}

__global__ void scatter_kernel(const int* __restrict__ coors, int n) {
    int i = blockIdx.x * blockDim.x + threadIdx.x;
    if (i < n) {
        int4 c = ((const int4*)coors)[i];  // (b, z, y, x)
        int lin = ((c.x * ZD + c.y) * YD + c.z) * XD + c.w;
        g_grid[lin] = i;
    }
}

// ---------------------------------------------------------------------------
// Layer 1: SubMConv3d k=3 pad=1, CIN=16 -> C1=32, fused BN+ReLU
// Block: 512 threads = 16 warps, each warp owns 8 rows, lane = output channel.
// Weights in shared, transposed to [k][co][ci], 128B rows, XOR-swizzled chunks.
// ---------------------------------------------------------------------------
extern __shared__ float smw[];

#define ROWVALID 64   // mask bit: this row exists

__global__ __launch_bounds__(512) void conv1_kernel(
    const float* __restrict__ feat, const int* __restrict__ coors,
    const float* __restrict__ W1,
    const float* __restrict__ g1, const float* __restrict__ b1,
    const float* __restrict__ m1, const float* __restrict__ v1,
    int n)
{
    // Stage W1[k][ci][co] -> smw[(k*32+co)*32 + (chunk^(co&7))*4 + pos], chunk=ci/4
    for (int e = threadIdx.x; e < 27 * CIN * C1; e += blockDim.x) {
        int k   = e / (CIN * C1);
        int rem = e % (CIN * C1);
        int ci  = rem / C1;
        int co  = rem % C1;
        int chunk = ci >> 2, pos = ci & 3;
        int sch = chunk ^ (co & 7);
        smw[(k * 32 + co) * 32 + sch * 4 + pos] = W1[e];
    }
    __syncthreads();

    int warp = threadIdx.x >> 5;
    int lane = threadIdx.x & 31;
    int row0 = blockIdx.x * 128 + warp * 8;

    // Lanes 0..7 each prep one row: linear base coord + boundary mask
    int mylin = 0, mymask = 0;
    if (lane < 8) {
        int r = row0 + lane;
        if (r < n) {
            int4 c = ((const int4*)coors)[r];  // (b, z, y, x)
            mylin  = ((c.x * ZD + c.y) * YD + c.z) * XD + c.w;
            mymask = (c.y > 0)             |
                     ((c.y < ZD - 1) << 1) |
                     ((c.z > 0)      << 2) |
                     ((c.z < YD - 1) << 3) |
                     ((c.w > 0)      << 4) |
                     ((c.w < XD - 1) << 5) |
                     ROWVALID;
        }
    }
    int lin_[8], msk_[8];
    #pragma unroll
    for (int r = 0; r < 8; r++) {
        lin_[r] = __shfl_sync(0xffffffffu, mylin, r);
        msk_[r] = __shfl_sync(0xffffffffu, mymask, r);
    }

    float acc[8];
    #pragma unroll
    for (int r = 0; r < 8; r++) acc[r] = 0.f;

    const float4* feat4 = (const float4*)feat;
    int swz = (lane & 7) * 4;  // word offset of swizzle base

    int k = 0;
    #pragma unroll 1
    for (int dz = -1; dz <= 1; dz++) {
        #pragma unroll 1
        for (int dy = -1; dy <= 1; dy++) {
            #pragma unroll 1
            for (int dx = -1; dx <= 1; dx++, k++) {
                int koff = (dz * YD + dy) * XD + dx;
                int req  = ((dz < 0 ? 1 : 0) | (dz > 0 ? 2 : 0) |
                            (dy < 0 ? 4 : 0) | (dy > 0 ? 8 : 0) |
                            (dx < 0 ? 16 : 0) | (dx > 0 ? 32 : 0)) | ROWVALID;
                // probe all 8 rows first (independent LDGs -> MLP)
                int idx[8];
                #pragma unroll
                for (int r = 0; r < 8; r++) {
                    bool v = (msk_[r] & req) == req;
                    idx[r] = v ? __ldg(&g_grid[lin_[r] + koff]) : -1;
                }
                const float* wrow = &smw[(k * 32 + lane) * 32];
                #pragma unroll
                for (int r = 0; r < 8; r++) {
                    if (idx[r] >= 0) {  // warp-uniform branch (~85% skipped)
                        #pragma unroll
                        for (int c = 0; c < 4; c++) {
                            float4 w = *(const float4*)&wrow[(c * 4) ^ swz];
                            float4 f = __ldg(&feat4[idx[r] * 4 + c]);
                            acc[r] = fmaf(f.x, w.x, acc[r]);
                            acc[r] = fmaf(f.y, w.y, acc[r]);
                            acc[r] = fmaf(f.z, w.z, acc[r]);
                            acc[r] = fmaf(f.w, w.w, acc[r]);
                        }
                    }
                }
            }
        }
    }

    // fused BN + ReLU, store f1
    float s  = g1[lane] * rsqrtf(v1[lane] + BN_EPS);
    float sh = b1[lane] - m1[lane] * s;
    #pragma unroll
    for (int r = 0; r < 8; r++) {
        int row = row0 + r;
        if (row < n) {
            float o = fmaf(acc[r], s, sh);
            g_f1[row * C1 + lane] = o > 0.f ? o : 0.f;
        }
    }
}

// ---------------------------------------------------------------------------
// Layer 2: SparseConv3d k=3 s=2 pad=(0,1,1), C1=32 -> C2=64, fused BN+ReLU
// Block: 512 threads = 16 warps, warp owns 8 rows; lane handles cout {lane, lane+32}.
// NOTE: base lin may be legitimately negative (y0/x0 = -1 at oy/ox = 0); row
// validity is carried in the ROWVALID mask bit, never inferred from lin's sign.
// ---------------------------------------------------------------------------
__global__ __launch_bounds__(512) void conv2_kernel(
    const int* __restrict__ ocoors, const float* __restrict__ W2,
    const float* __restrict__ g2, const float* __restrict__ b2,
    const float* __restrict__ m2, const float* __restrict__ v2,
    float* __restrict__ out, int m)
{
    // Stage W2[k][ci][co] -> smw[(k*64+co)*32 + (chunk^(co&7))*4 + pos], chunk=ci/4 (0..7)
    for (int e = threadIdx.x; e < 27 * C1 * C2; e += blockDim.x) {
        int k   = e / (C1 * C2);
        int rem = e % (C1 * C2);
        int ci  = rem / C2;
        int co  = rem % C2;
        int chunk = ci >> 2, pos = ci & 3;
        int sch = chunk ^ (co & 7);
        smw[(k * 64 + co) * 32 + sch * 4 + pos] = W2[e];
    }
    __syncthreads();

    int warp = threadIdx.x >> 5;
    int lane = threadIdx.x & 31;
    int row0 = blockIdx.x * 128 + warp * 8;

    int mylin = 0, mymask = 0;
    if (lane < 8) {
        int r = row0 + lane;
        if (r < m) {
            int4 c = ((const int4*)ocoors)[r];  // (b, oz, oy, ox)
            int z0 = c.y * 2;        // jz in 0..2 -> z in [0,20], always in range
            int y0 = c.z * 2 - 1;    // jy=0 needs oy>0
            int x0 = c.w * 2 - 1;    // jx=0 needs ox>0
            mylin  = ((c.x * ZD + z0) * YD + y0) * XD + x0;   // may be < 0; still correct
            mymask = (c.z > 0) | ((c.w > 0) << 1) | ROWVALID;
        }
    }
    int lin_[8], msk_[8];
    #pragma unroll
    for (int r = 0; r < 8; r++) {
        lin_[r] = __shfl_sync(0xffffffffu, mylin, r);
        msk_[r] = __shfl_sync(0xffffffffu, mymask, r);
    }

    float acc[8][2];
    #pragma unroll
    for (int r = 0; r < 8; r++) { acc[r][0] = 0.f; acc[r][1] = 0.f; }

    const float4* f14 = (const float4*)g_f1;
    int swz = (lane & 7) * 4;

    int k = 0;
    #pragma unroll 1
    for (int jz = 0; jz < 3; jz++) {
        #pragma unroll 1
        for (int jy = 0; jy < 3; jy++) {
            #pragma unroll 1
            for (int jx = 0; jx < 3; jx++, k++) {
                int koff = (jz * YD + jy) * XD + jx;
                int req  = ((jy == 0 ? 1 : 0) | (jx == 0 ? 2 : 0)) | ROWVALID;
                int idx[8];
                #pragma unroll
                for (int r = 0; r < 8; r++) {
                    bool v = (msk_[r] & req) == req;
                    idx[r] = v ? __ldg(&g_grid[lin_[r] + koff]) : -1;
                }
                const float* wrow0 = &smw[(k * 64 + lane) * 32];
                const float* wrow1 = wrow0 + 32 * 32;  // co = lane+32
                #pragma unroll
                for (int r = 0; r < 8; r++) {
                    if (idx[r] >= 0) {  // warp-uniform, ~85% skipped
                        #pragma unroll
                        for (int c = 0; c < 8; c++) {
                            float4 f  = __ldg(&f14[idx[r] * 8 + c]);
                            float4 w0 = *(const float4*)&wrow0[(c * 4) ^ swz];
                            float4 w1 = *(const float4*)&wrow1[(c * 4) ^ swz];
                            acc[r][0] = fmaf(f.x, w0.x, acc[r][0]);
                            acc[r][0] = fmaf(f.y, w0.y, acc[r][0]);
                            acc[r][0] = fmaf(f.z, w0.z, acc[r][0]);
                            acc[r][0] = fmaf(f.w, w0.w, acc[r][0]);
                            acc[r][1] = fmaf(f.x, w1.x, acc[r][1]);
                            acc[r][1] = fmaf(f.y, w1.y, acc[r][1]);
                            acc[r][1] = fmaf(f.z, w1.z, acc[r][1]);
                            acc[r][1] = fmaf(f.w, w1.w, acc[r][1]);
                        }
                    }
                }
            }
        }
    }

    float s0  = g2[lane]      * rsqrtf(v2[lane]      + BN_EPS);
    float sh0 = b2[lane]      - m2[lane]      * s0;
    float s1  = g2[lane + 32] * rsqrtf(v2[lane + 32] + BN_EPS);
    float sh1 = b2[lane + 32] - m2[lane + 32] * s1;
    #pragma unroll
    for (int r = 0; r < 8; r++) {
        int row = row0 + r;
        if (row < m) {
            float o0 = fmaf(acc[r][0], s0, sh0);
            float o1 = fmaf(acc[r][1], s1, sh1);
            out[row * C2 + lane]      = o0 > 0.f ? o0 : 0.f;
            out[row * C2 + lane + 32] = o1 > 0.f ? o1 : 0.f;
        }
    }
}

// ---------------------------------------------------------------------------
// Tail: fill everything past f2 (out_coors as float, batch_size) if the
// harness flattened the full reference tuple into d_out.
// ---------------------------------------------------------------------------
__global__ void tail_kernel(const int* __restrict__ ocoors,
                            const int* __restrict__ bsz,
                            float* __restrict__ out, int m, int total)
{
    int i = blockIdx.x * blockDim.x + threadIdx.x + m * 64;
    if (i >= total) return;
    int j = i - m * 64;
    float v;
    if (j < m * 4)       v = (float)ocoors[j];
    else if (j == m * 4) v = (float)bsz[0];
    else                 v = 0.f;
    out[i] = v;
}

// ---------------------------------------------------------------------------
extern "C" void kernel_launch(void* const* d_in, const int* in_sizes, int n_in,
                              void* d_out, int out_size)
{
    const float* feat   = (const float*)d_in[0];
    const int*   coors  = (const int*)d_in[1];
    const int*   ocoors = (const int*)d_in[2];
    const float* W1     = (const float*)d_in[3];
    const float* g1     = (const float*)d_in[4];
    const float* b1     = (const float*)d_in[5];
    const float* m1     = (const float*)d_in[6];
    const float* v1     = (const float*)d_in[7];
    const float* W2     = (const float*)d_in[8];
    const float* g2     = (const float*)d_in[9];
    const float* b2     = (const float*)d_in[10];
    const float* m2     = (const float*)d_in[11];
    const float* v2     = (const float*)d_in[12];
    const int*   bsz    = (const int*)d_in[13];

    int n = in_sizes[0] / CIN;
    int m = in_sizes[2] / 4;

    fill_grid_kernel<<<(GRID_SZ / 4 + 255) / 256, 256>>>();
    scatter_kernel<<<(n + 255) / 256, 256>>>(coors, n);

    int smem1 = 27 * C1 * 32 * (int)sizeof(float);   // 110,592 B
    cudaFuncSetAttribute(conv1_kernel, cudaFuncAttributeMaxDynamicSharedMemorySize, smem1);
    conv1_kernel<<<(n + 127) / 128, 512, smem1>>>(feat, coors, W1, g1, b1, m1, v1, n);

    int smem2 = 27 * C2 * 32 * (int)sizeof(float);   // 221,184 B
    cudaFuncSetAttribute(conv2_kernel, cudaFuncAttributeMaxDynamicSharedMemorySize, smem2);
    conv2_kernel<<<(m + 127) / 128, 512, smem2>>>(ocoors, W2, g2, b2, m2, v2,
                                                  (float*)d_out, m);

    int tail = out_size - m * 64;
    if (tail > 0) {
        tail_kernel<<<(tail + 255) / 256, 256>>>(ocoors, bsz, (float*)d_out, m, out_size);
    }
}

// round 3
// speedup vs baseline: 1.1025x; 1.1025x over previous
#include <cuda_runtime.h>
#include <cuda_bf16.h>

#define ZD 21
#define YD 256
#define XD 256
#define CIN 16
#define C1 32
#define C2 64
#define BN_EPS 1e-3f
#define GRID_SZ (2 * ZD * YD * XD)   // 2,752,512
#define NMAX 400000
#define FULLW 0xffffffffu
#define ROWVALID 64   // mask bit: this row exists

// Scratch (allocs are forbidden; __device__ globals are the sanctioned path)
__device__ int   g_grid[GRID_SZ];
__device__ float g_f1[NMAX * C1];

// ---------------------------------------------------------------------------
// Hash-grid build
// ---------------------------------------------------------------------------
__global__ void fill_grid_kernel() {
    int i = blockIdx.x * blockDim.x + threadIdx.x;
    if (i < GRID_SZ / 4) {
        ((int4*)g_grid)[i] = make_int4(-1, -1, -1, -1);
    }
}

__global__ void scatter_kernel(const int* __restrict__ coors, int n) {
    int i = blockIdx.x * blockDim.x + threadIdx.x;
    if (i < n) {
        int4 c = ((const int4*)coors)[i];  // (b, z, y, x)
        int lin = ((c.x * ZD + c.y) * YD + c.z) * XD + c.w;
        g_grid[lin] = i;
    }
}

// ---------------------------------------------------------------------------
// Probes (per-lane; lanes holding no row have msk=0 -> always -1)
// ---------------------------------------------------------------------------
__device__ __forceinline__ int probe1(int k, int lin, int msk) {
    int dz = k / 9 - 1, dy = (k / 3) % 3 - 1, dx = k % 3 - 1;
    int req = ((dz < 0) ? 1 : 0) | ((dz > 0) ? 2 : 0) |
              ((dy < 0) ? 4 : 0) | ((dy > 0) ? 8 : 0) |
              ((dx < 0) ? 16 : 0) | ((dx > 0) ? 32 : 0) | ROWVALID;
    int koff = (dz * YD + dy) * XD + dx;
    return ((msk & req) == req) ? __ldg(&g_grid[lin + koff]) : -1;
}

__device__ __forceinline__ int probe2(int k, int lin, int msk) {
    int jz = k / 9, jy = (k / 3) % 3, jx = k % 3;
    int req = ((jy == 0) ? 1 : 0) | ((jx == 0) ? 2 : 0) | ROWVALID;
    int koff = (jz * YD + jy) * XD + jx;
    return ((msk & req) == req) ? __ldg(&g_grid[lin + koff]) : -1;
}

extern __shared__ float smw[];

// ---------------------------------------------------------------------------
// Layer 1: SubMConv3d k=3 pad=1, CIN=16 -> C1=32, fused BN+ReLU
// 512 thr = 16 warps; warp owns 16 rows, lane = cout. k-outer loop with
// per-k register-resident weights and probe prefetch.
// ---------------------------------------------------------------------------
__global__ __launch_bounds__(512) void conv1_kernel(
    const float* __restrict__ feat, const int* __restrict__ coors,
    const float* __restrict__ W1,
    const float* __restrict__ g1, const float* __restrict__ b1,
    const float* __restrict__ m1, const float* __restrict__ v1,
    int n)
{
    // Stage W1[k][ci][co] -> smw[(k*32+co)*32 + ((chunk^(co&7))*4 + pos], chunk=ci/4
    for (int e = threadIdx.x; e < 27 * CIN * C1; e += blockDim.x) {
        int k   = e / (CIN * C1);
        int rem = e % (CIN * C1);
        int ci  = rem / C1;
        int co  = rem % C1;
        int chunk = ci >> 2, pos = ci & 3;
        int sch = chunk ^ (co & 7);
        smw[(k * 32 + co) * 32 + sch * 4 + pos] = W1[e];
    }
    __syncthreads();

    int warp = threadIdx.x >> 5;
    int lane = threadIdx.x & 31;
    int row0 = blockIdx.x * 256 + warp * 16;

    int lin = 0, msk = 0;
    if (lane < 16) {
        int r = row0 + lane;
        if (r < n) {
            int4 c = ((const int4*)coors)[r];  // (b, z, y, x)
            lin = ((c.x * ZD + c.y) * YD + c.z) * XD + c.w;
            msk = (c.y > 0)             |
                  ((c.y < ZD - 1) << 1) |
                  ((c.z > 0)      << 2) |
                  ((c.z < YD - 1) << 3) |
                  ((c.w > 0)      << 4) |
                  ((c.w < XD - 1) << 5) |
                  ROWVALID;
        }
    }

    float acc[16];
    #pragma unroll
    for (int r = 0; r < 16; r++) acc[r] = 0.f;

    const float4* feat4 = (const float4*)feat;
    int swz = (lane & 7) * 4;

    int cur = probe1(0, lin, msk);
    #pragma unroll 1
    for (int k = 0; k < 27; k++) {
        int nxt = (k < 26) ? probe1(k + 1, lin, msk) : -1;
        unsigned mask = __ballot_sync(FULLW, cur >= 0) & 0xffffu;
        if (mask) {
            const float* wrow = &smw[(k * 32 + lane) * 32];
            float4 w0 = *(const float4*)&wrow[(0 * 4) ^ swz];
            float4 w1 = *(const float4*)&wrow[(1 * 4) ^ swz];
            float4 w2 = *(const float4*)&wrow[(2 * 4) ^ swz];
            float4 w3 = *(const float4*)&wrow[(3 * 4) ^ swz];
            #pragma unroll
            for (int r = 0; r < 16; r++) {
                if ((mask >> r) & 1) {   // warp-uniform
                    int idx = __shfl_sync(FULLW, cur, r);
                    float4 f0 = __ldg(&feat4[idx * 4 + 0]);
                    float4 f1 = __ldg(&feat4[idx * 4 + 1]);
                    float4 f2 = __ldg(&feat4[idx * 4 + 2]);
                    float4 f3 = __ldg(&feat4[idx * 4 + 3]);
                    float a = acc[r];
                    a = fmaf(f0.x, w0.x, a); a = fmaf(f0.y, w0.y, a);
                    a = fmaf(f0.z, w0.z, a); a = fmaf(f0.w, w0.w, a);
                    a = fmaf(f1.x, w1.x, a); a = fmaf(f1.y, w1.y, a);
                    a = fmaf(f1.z, w1.z, a); a = fmaf(f1.w, w1.w, a);
                    a = fmaf(f2.x, w2.x, a); a = fmaf(f2.y, w2.y, a);
                    a = fmaf(f2.z, w2.z, a); a = fmaf(f2.w, w2.w, a);
                    a = fmaf(f3.x, w3.x, a); a = fmaf(f3.y, w3.y, a);
                    a = fmaf(f3.z, w3.z, a); a = fmaf(f3.w, w3.w, a);
                    acc[r] = a;
                }
            }
        }
        cur = nxt;
    }

    float s  = g1[lane] * rsqrtf(v1[lane] + BN_EPS);
    float sh = b1[lane] - m1[lane] * s;
    #pragma unroll
    for (int r = 0; r < 16; r++) {
        int row = row0 + r;
        if (row < n) {
            float o = fmaf(acc[r], s, sh);
            g_f1[row * C1 + lane] = o > 0.f ? o : 0.f;
        }
    }
}

// ---------------------------------------------------------------------------
// Layer 2: SparseConv3d k=3 s=2 pad=(0,1,1), C1=32 -> C2=64, fused BN+ReLU
// 512 thr = 16 warps; warp pair shares 16 rows, each warp does one cout half.
// NOTE: base lin may be legitimately negative (y0/x0=-1 at oy/ox=0); validity
// lives in the ROWVALID mask bit, never in lin's sign.
// ---------------------------------------------------------------------------
__global__ __launch_bounds__(512) void conv2_kernel(
    const int* __restrict__ ocoors, const float* __restrict__ W2,
    const float* __restrict__ g2, const float* __restrict__ b2,
    const float* __restrict__ m2, const float* __restrict__ v2,
    float* __restrict__ out, int m)
{
    // Stage W2[k][ci][co] -> smw[(k*64+co)*32 + (chunk^(co&7))*4 + pos]
    for (int e = threadIdx.x; e < 27 * C1 * C2; e += blockDim.x) {
        int k   = e / (C1 * C2);
        int rem = e % (C1 * C2);
        int ci  = rem / C2;
        int co  = rem % C2;
        int chunk = ci >> 2, pos = ci & 3;
        int sch = chunk ^ (co & 7);
        smw[(k * 64 + co) * 32 + sch * 4 + pos] = W2[e];
    }
    __syncthreads();

    int warp = threadIdx.x >> 5;
    int lane = threadIdx.x & 31;
    int half = warp & 1;                      // cout half: lane -> co = half*32+lane
    int row0 = blockIdx.x * 128 + (warp >> 1) * 16;

    int lin = 0, msk = 0;
    if (lane < 16) {
        int r = row0 + lane;
        if (r < m) {
            int4 c = ((const int4*)ocoors)[r];  // (b, oz, oy, ox)
            int z0 = c.y * 2;
            int y0 = c.z * 2 - 1;
            int x0 = c.w * 2 - 1;
            lin = ((c.x * ZD + z0) * YD + y0) * XD + x0;   // may be < 0, OK
            msk = (c.z > 0) | ((c.w > 0) << 1) | ROWVALID;
        }
    }

    float acc[16];
    #pragma unroll
    for (int r = 0; r < 16; r++) acc[r] = 0.f;

    const float4* f14 = (const float4*)g_f1;
    int swz = (lane & 7) * 4;

    int cur = probe2(0, lin, msk);
    #pragma unroll 1
    for (int k = 0; k < 27; k++) {
        int nxt = (k < 26) ? probe2(k + 1, lin, msk) : -1;
        unsigned mask = __ballot_sync(FULLW, cur >= 0) & 0xffffu;
        if (mask) {
            const float* wrow = &smw[(k * 64 + half * 32 + lane) * 32];
            float4 w0 = *(const float4*)&wrow[(0 * 4) ^ swz];
            float4 w1 = *(const float4*)&wrow[(1 * 4) ^ swz];
            float4 w2 = *(const float4*)&wrow[(2 * 4) ^ swz];
            float4 w3 = *(const float4*)&wrow[(3 * 4) ^ swz];
            float4 w4 = *(const float4*)&wrow[(4 * 4) ^ swz];
            float4 w5 = *(const float4*)&wrow[(5 * 4) ^ swz];
            float4 w6 = *(const float4*)&wrow[(6 * 4) ^ swz];
            float4 w7 = *(const float4*)&wrow[(7 * 4) ^ swz];
            #pragma unroll
            for (int r = 0; r < 16; r++) {
                if ((mask >> r) & 1) {   // warp-uniform
                    int idx = __shfl_sync(FULLW, cur, r);
                    float a = acc[r];
                    float4 f;
                    f = __ldg(&f14[idx * 8 + 0]);
                    a = fmaf(f.x, w0.x, a); a = fmaf(f.y, w0.y, a);
                    a = fmaf(f.z, w0.z, a); a = fmaf(f.w, w0.w, a);
                    f = __ldg(&f14[idx * 8 + 1]);
                    a = fmaf(f.x, w1.x, a); a = fmaf(f.y, w1.y, a);
                    a = fmaf(f.z, w1.z, a); a = fmaf(f.w, w1.w, a);
                    f = __ldg(&f14[idx * 8 + 2]);
                    a = fmaf(f.x, w2.x, a); a = fmaf(f.y, w2.y, a);
                    a = fmaf(f.z, w2.z, a); a = fmaf(f.w, w2.w, a);
                    f = __ldg(&f14[idx * 8 + 3]);
                    a = fmaf(f.x, w3.x, a); a = fmaf(f.y, w3.y, a);
                    a = fmaf(f.z, w3.z, a); a = fmaf(f.w, w3.w, a);
                    f = __ldg(&f14[idx * 8 + 4]);
                    a = fmaf(f.x, w4.x, a); a = fmaf(f.y, w4.y, a);
                    a = fmaf(f.z, w4.z, a); a = fmaf(f.w, w4.w, a);
                    f = __ldg(&f14[idx * 8 + 5]);
                    a = fmaf(f.x, w5.x, a); a = fmaf(f.y, w5.y, a);
                    a = fmaf(f.z, w5.z, a); a = fmaf(f.w, w5.w, a);
                    f = __ldg(&f14[idx * 8 + 6]);
                    a = fmaf(f.x, w6.x, a); a = fmaf(f.y, w6.y, a);
                    a = fmaf(f.z, w6.z, a); a = fmaf(f.w, w6.w, a);
                    f = __ldg(&f14[idx * 8 + 7]);
                    a = fmaf(f.x, w7.x, a); a = fmaf(f.y, w7.y, a);
                    a = fmaf(f.z, w7.z, a); a = fmaf(f.w, w7.w, a);
                    acc[r] = a;
                }
            }
        }
        cur = nxt;
    }

    int co = half * 32 + lane;
    float s  = g2[co] * rsqrtf(v2[co] + BN_EPS);
    float sh = b2[co] - m2[co] * s;
    #pragma unroll
    for (int r = 0; r < 16; r++) {
        int row = row0 + r;
        if (row < m) {
            float o = fmaf(acc[r], s, sh);
            out[row * C2 + co] = o > 0.f ? o : 0.f;
        }
    }
}

// ---------------------------------------------------------------------------
// Tail: fill everything past f2 (out_coors as float, batch_size) if the
// harness flattened the full reference tuple into d_out.
// ---------------------------------------------------------------------------
__global__ void tail_kernel(const int* __restrict__ ocoors,
                            const int* __restrict__ bsz,
                            float* __restrict__ out, int m, int total)
{
    int i = blockIdx.x * blockDim.x + threadIdx.x + m * 64;
    if (i >= total) return;
    int j = i - m * 64;
    float v;
    if (j < m * 4)       v = (float)ocoors[j];
    else if (j == m * 4) v = (float)bsz[0];
    else                 v = 0.f;
    out[i] = v;
}

// ---------------------------------------------------------------------------
extern "C" void kernel_launch(void* const* d_in, const int* in_sizes, int n_in,
                              void* d_out, int out_size)
{
    const float* feat   = (const float*)d_in[0];
    const int*   coors  = (const int*)d_in[1];
    const int*   ocoors = (const int*)d_in[2];
    const float* W1     = (const float*)d_in[3];
    const float* g1     = (const float*)d_in[4];
    const float* b1     = (const float*)d_in[5];
    const float* m1     = (const float*)d_in[6];
    const float* v1     = (const float*)d_in[7];
    const float* W2     = (const float*)d_in[8];
    const float* g2     = (const float*)d_in[9];
    const float* b2     = (const float*)d_in[10];
    const float* m2     = (const float*)d_in[11];
    const float* v2     = (const float*)d_in[12];
    const int*   bsz    = (const int*)d_in[13];

    int n = in_sizes[0] / CIN;
    int m = in_sizes[2] / 4;

    fill_grid_kernel<<<(GRID_SZ / 4 + 255) / 256, 256>>>();
    scatter_kernel<<<(n + 255) / 256, 256>>>(coors, n);

    int smem1 = 27 * C1 * 32 * (int)sizeof(float);   // 110,592 B
    cudaFuncSetAttribute(conv1_kernel, cudaFuncAttributeMaxDynamicSharedMemorySize, smem1);
    conv1_kernel<<<(n + 255) / 256, 512, smem1>>>(feat, coors, W1, g1, b1, m1, v1, n);

    int smem2 = 27 * C2 * 32 * (int)sizeof(float);   // 221,184 B
    cudaFuncSetAttribute(conv2_kernel, cudaFuncAttributeMaxDynamicSharedMemorySize, smem2);
    conv2_kernel<<<(m + 127) / 128, 512, smem2>>>(ocoors, W2, g2, b2, m2, v2,
                                                  (float*)d_out, m);

    int tail = out_size - m * 64;
    if (tail > 0) {
        tail_kernel<<<(tail + 255) / 256, 256>>>(ocoors, bsz, (float*)d_out, m, out_size);
    }
}

// round 4
// speedup vs baseline: 1.7724x; 1.6077x over previous
#include <cuda_runtime.h>
#include <cuda_bf16.h>

#define ZD 21
#define YD 256
#define XD 256
#define CIN 16
#define C1 32
#define C2 64
#define BN_EPS 1e-3f
#define GRID_SZ (2 * ZD * YD * XD)   // 2,752,512
#define NMAX 400000
#define FULLW 0xffffffffu
#define ROWVALID 64   // mask bit: this row exists

// Scratch (allocs are forbidden; __device__ globals are the sanctioned path)
__device__ int   g_grid[GRID_SZ];
__device__ float g_f1[NMAX * C1];

// ---------------------------------------------------------------------------
// Hash-grid build
// ---------------------------------------------------------------------------
__global__ void fill_grid_kernel() {
    int i = blockIdx.x * blockDim.x + threadIdx.x;
    if (i < GRID_SZ / 4) {
        ((int4*)g_grid)[i] = make_int4(-1, -1, -1, -1);
    }
}

__global__ void scatter_kernel(const int* __restrict__ coors, int n) {
    int i = blockIdx.x * blockDim.x + threadIdx.x;
    if (i < n) {
        int4 c = ((const int4*)coors)[i];  // (b, z, y, x)
        int lin = ((c.x * ZD + c.y) * YD + c.z) * XD + c.w;
        g_grid[lin] = i;
    }
}

// ---------------------------------------------------------------------------
// Probes (per-lane; lanes holding no row have msk=0 -> always -1)
// ---------------------------------------------------------------------------
__device__ __forceinline__ int probe1(int k, int lin, int msk) {
    int dz = k / 9 - 1, dy = (k / 3) % 3 - 1, dx = k % 3 - 1;
    int req = ((dz < 0) ? 1 : 0) | ((dz > 0) ? 2 : 0) |
              ((dy < 0) ? 4 : 0) | ((dy > 0) ? 8 : 0) |
              ((dx < 0) ? 16 : 0) | ((dx > 0) ? 32 : 0) | ROWVALID;
    int koff = (dz * YD + dy) * XD + dx;
    return ((msk & req) == req) ? __ldg(&g_grid[lin + koff]) : -1;
}

__device__ __forceinline__ int probe2(int k, int lin, int msk) {
    int jz = k / 9, jy = (k / 3) % 3, jx = k % 3;
    int req = ((jy == 0) ? 1 : 0) | ((jx == 0) ? 2 : 0) | ROWVALID;
    int koff = (jz * YD + jy) * XD + jx;
    return ((msk & req) == req) ? __ldg(&g_grid[lin + koff]) : -1;
}

extern __shared__ float smw[];

// ---------------------------------------------------------------------------
// Layer 1: SubMConv3d k=3 pad=1, CIN=16 -> C1=32, fused BN+ReLU
// 512 thr = 16 warps, 2 blocks/SM (smem 110.6KB, regs <=64).
// Warp owns 16 rows, lane = cout. k-outer, per-k register weights, probe
// prefetch, statically-unrolled masked inner loop.
// ---------------------------------------------------------------------------
__global__ __launch_bounds__(512, 2) void conv1_kernel(
    const float* __restrict__ feat, const int* __restrict__ coors,
    const float* __restrict__ W1,
    const float* __restrict__ g1, const float* __restrict__ b1,
    const float* __restrict__ m1, const float* __restrict__ v1,
    int n)
{
    // Stage W1[k][ci][co] -> smw[(k*32+co)*32 + (chunk^(co&7))*4 + pos], chunk=ci/4
    for (int e = threadIdx.x; e < 27 * CIN * C1; e += blockDim.x) {
        int k   = e / (CIN * C1);
        int rem = e % (CIN * C1);
        int ci  = rem / C1;
        int co  = rem % C1;
        int chunk = ci >> 2, pos = ci & 3;
        int sch = chunk ^ (co & 7);
        smw[(k * 32 + co) * 32 + sch * 4 + pos] = W1[e];
    }
    __syncthreads();

    int warp = threadIdx.x >> 5;
    int lane = threadIdx.x & 31;
    int row0 = blockIdx.x * 256 + warp * 16;

    int lin = 0, msk = 0;
    if (lane < 16) {
        int r = row0 + lane;
        if (r < n) {
            int4 c = ((const int4*)coors)[r];  // (b, z, y, x)
            lin = ((c.x * ZD + c.y) * YD + c.z) * XD + c.w;
            msk = (c.y > 0)             |
                  ((c.y < ZD - 1) << 1) |
                  ((c.z > 0)      << 2) |
                  ((c.z < YD - 1) << 3) |
                  ((c.w > 0)      << 4) |
                  ((c.w < XD - 1) << 5) |
                  ROWVALID;
        }
    }

    float acc[16];
    #pragma unroll
    for (int r = 0; r < 16; r++) acc[r] = 0.f;

    const float4* feat4 = (const float4*)feat;
    int swz = (lane & 7) * 4;

    int cur = probe1(0, lin, msk);
    #pragma unroll 1
    for (int k = 0; k < 27; k++) {
        int nxt = (k < 26) ? probe1(k + 1, lin, msk) : -1;
        unsigned mask = __ballot_sync(FULLW, cur >= 0) & 0xffffu;
        if (mask) {
            const float* wrow = &smw[(k * 32 + lane) * 32];
            float4 w0 = *(const float4*)&wrow[(0 * 4) ^ swz];
            float4 w1 = *(const float4*)&wrow[(1 * 4) ^ swz];
            float4 w2 = *(const float4*)&wrow[(2 * 4) ^ swz];
            float4 w3 = *(const float4*)&wrow[(3 * 4) ^ swz];
            #pragma unroll
            for (int r = 0; r < 16; r++) {
                if ((mask >> r) & 1) {   // warp-uniform
                    int idx = __shfl_sync(FULLW, cur, r);
                    float4 f0 = __ldg(&feat4[idx * 4 + 0]);
                    float4 f1 = __ldg(&feat4[idx * 4 + 1]);
                    float4 f2 = __ldg(&feat4[idx * 4 + 2]);
                    float4 f3 = __ldg(&feat4[idx * 4 + 3]);
                    float a = acc[r];
                    a = fmaf(f0.x, w0.x, a); a = fmaf(f0.y, w0.y, a);
                    a = fmaf(f0.z, w0.z, a); a = fmaf(f0.w, w0.w, a);
                    a = fmaf(f1.x, w1.x, a); a = fmaf(f1.y, w1.y, a);
                    a = fmaf(f1.z, w1.z, a); a = fmaf(f1.w, w1.w, a);
                    a = fmaf(f2.x, w2.x, a); a = fmaf(f2.y, w2.y, a);
                    a = fmaf(f2.z, w2.z, a); a = fmaf(f2.w, w2.w, a);
                    a = fmaf(f3.x, w3.x, a); a = fmaf(f3.y, w3.y, a);
                    a = fmaf(f3.z, w3.z, a); a = fmaf(f3.w, w3.w, a);
                    acc[r] = a;
                }
            }
        }
        cur = nxt;
    }

    float s  = g1[lane] * rsqrtf(v1[lane] + BN_EPS);
    float sh = b1[lane] - m1[lane] * s;
    #pragma unroll
    for (int r = 0; r < 16; r++) {
        int row = row0 + r;
        if (row < n) {
            float o = fmaf(acc[r], s, sh);
            g_f1[row * C1 + lane] = o > 0.f ? o : 0.f;
        }
    }
}

// ---------------------------------------------------------------------------
// Layer 2: SparseConv3d k=3 s=2 pad=(0,1,1), C1=32 -> C2=64, fused BN+ReLU
// Cout halves are split ACROSS BLOCKS: block = (row_tile, half). Each block
// stages only its half of W2 (110.6KB smem) -> 2 blocks/SM, 32 warps.
// 512 thr = 16 warps; warp owns 16 rows, lane = local cout.
// NOTE: base lin may be legitimately negative (y0/x0=-1 at oy/ox=0); validity
// lives in the ROWVALID mask bit, never in lin's sign.
// ---------------------------------------------------------------------------
__global__ __launch_bounds__(512, 2) void conv2_kernel(
    const int* __restrict__ ocoors, const float* __restrict__ W2,
    const float* __restrict__ g2, const float* __restrict__ b2,
    const float* __restrict__ m2, const float* __restrict__ v2,
    float* __restrict__ out, int m)
{
    int half = blockIdx.x & 1;               // which 32-cout half this block owns

    // Stage W2[k][ci][half*32+col] -> smw[(k*32+col)*32 + (chunk^(col&7))*4 + pos]
    for (int e = threadIdx.x; e < 27 * C1 * 32; e += blockDim.x) {
        int k   = e / (C1 * 32);
        int rem = e % (C1 * 32);
        int ci  = rem / 32;
        int col = rem % 32;
        int chunk = ci >> 2, pos = ci & 3;
        int sch = chunk ^ (col & 7);
        smw[(k * 32 + col) * 32 + sch * 4 + pos] =
            W2[(k * C1 + ci) * C2 + half * 32 + col];
    }
    __syncthreads();

    int warp = threadIdx.x >> 5;
    int lane = threadIdx.x & 31;
    int row0 = (blockIdx.x >> 1) * 256 + warp * 16;

    int lin = 0, msk = 0;
    if (lane < 16) {
        int r = row0 + lane;
        if (r < m) {
            int4 c = ((const int4*)ocoors)[r];  // (b, oz, oy, ox)
            int z0 = c.y * 2;
            int y0 = c.z * 2 - 1;
            int x0 = c.w * 2 - 1;
            lin = ((c.x * ZD + z0) * YD + y0) * XD + x0;   // may be < 0, OK
            msk = (c.z > 0) | ((c.w > 0) << 1) | ROWVALID;
        }
    }

    float acc[16];
    #pragma unroll
    for (int r = 0; r < 16; r++) acc[r] = 0.f;

    const float4* f14 = (const float4*)g_f1;
    int swz = (lane & 7) * 4;

    int cur = probe2(0, lin, msk);
    #pragma unroll 1
    for (int k = 0; k < 27; k++) {
        int nxt = (k < 26) ? probe2(k + 1, lin, msk) : -1;
        unsigned mask = __ballot_sync(FULLW, cur >= 0) & 0xffffu;
        if (mask) {
            const float* wrow = &smw[(k * 32 + lane) * 32];
            float4 w0 = *(const float4*)&wrow[(0 * 4) ^ swz];
            float4 w1 = *(const float4*)&wrow[(1 * 4) ^ swz];
            float4 w2 = *(const float4*)&wrow[(2 * 4) ^ swz];
            float4 w3 = *(const float4*)&wrow[(3 * 4) ^ swz];
            float4 w4 = *(const float4*)&wrow[(4 * 4) ^ swz];
            float4 w5 = *(const float4*)&wrow[(5 * 4) ^ swz];
            float4 w6 = *(const float4*)&wrow[(6 * 4) ^ swz];
            float4 w7 = *(const float4*)&wrow[(7 * 4) ^ swz];
            #pragma unroll
            for (int r = 0; r < 16; r++) {
                if ((mask >> r) & 1) {   // warp-uniform
                    int idx = __shfl_sync(FULLW, cur, r);
                    float a = acc[r];
                    float4 f;
                    f = __ldg(&f14[idx * 8 + 0]);
                    a = fmaf(f.x, w0.x, a); a = fmaf(f.y, w0.y, a);
                    a = fmaf(f.z, w0.z, a); a = fmaf(f.w, w0.w, a);
                    f = __ldg(&f14[idx * 8 + 1]);
                    a = fmaf(f.x, w1.x, a); a = fmaf(f.y, w1.y, a);
                    a = fmaf(f.z, w1.z, a); a = fmaf(f.w, w1.w, a);
                    f = __ldg(&f14[idx * 8 + 2]);
                    a = fmaf(f.x, w2.x, a); a = fmaf(f.y, w2.y, a);
                    a = fmaf(f.z, w2.z, a); a = fmaf(f.w, w2.w, a);
                    f = __ldg(&f14[idx * 8 + 3]);
                    a = fmaf(f.x, w3.x, a); a = fmaf(f.y, w3.y, a);
                    a = fmaf(f.z, w3.z, a); a = fmaf(f.w, w3.w, a);
                    f = __ldg(&f14[idx * 8 + 4]);
                    a = fmaf(f.x, w4.x, a); a = fmaf(f.y, w4.y, a);
                    a = fmaf(f.z, w4.z, a); a = fmaf(f.w, w4.w, a);
                    f = __ldg(&f14[idx * 8 + 5]);
                    a = fmaf(f.x, w5.x, a); a = fmaf(f.y, w5.y, a);
                    a = fmaf(f.z, w5.z, a); a = fmaf(f.w, w5.w, a);
                    f = __ldg(&f14[idx * 8 + 6]);
                    a = fmaf(f.x, w6.x, a); a = fmaf(f.y, w6.y, a);
                    a = fmaf(f.z, w6.z, a); a = fmaf(f.w, w6.w, a);
                    f = __ldg(&f14[idx * 8 + 7]);
                    a = fmaf(f.x, w7.x, a); a = fmaf(f.y, w7.y, a);
                    a = fmaf(f.z, w7.z, a); a = fmaf(f.w, w7.w, a);
                    acc[r] = a;
                }
            }
        }
        cur = nxt;
    }

    int co = half * 32 + lane;
    float s  = g2[co] * rsqrtf(v2[co] + BN_EPS);
    float sh = b2[co] - m2[co] * s;
    #pragma unroll
    for (int r = 0; r < 16; r++) {
        int row = row0 + r;
        if (row < m) {
            float o = fmaf(acc[r], s, sh);
            out[row * C2 + co] = o > 0.f ? o : 0.f;
        }
    }
}

// ---------------------------------------------------------------------------
// Tail: fill everything past f2 (out_coors as float, batch_size) if the
// harness flattened the full reference tuple into d_out.
// ---------------------------------------------------------------------------
__global__ void tail_kernel(const int* __restrict__ ocoors,
                            const int* __restrict__ bsz,
                            float* __restrict__ out, int m, int total)
{
    int i = blockIdx.x * blockDim.x + threadIdx.x + m * 64;
    if (i >= total) return;
    int j = i - m * 64;
    float v;
    if (j < m * 4)       v = (float)ocoors[j];
    else if (j == m * 4) v = (float)bsz[0];
    else                 v = 0.f;
    out[i] = v;
}

// ---------------------------------------------------------------------------
extern "C" void kernel_launch(void* const* d_in, const int* in_sizes, int n_in,
                              void* d_out, int out_size)
{
    const float* feat   = (const float*)d_in[0];
    const int*   coors  = (const int*)d_in[1];
    const int*   ocoors = (const int*)d_in[2];
    const float* W1     = (const float*)d_in[3];
    const float* g1     = (const float*)d_in[4];
    const float* b1     = (const float*)d_in[5];
    const float* m1     = (const float*)d_in[6];
    const float* v1     = (const float*)d_in[7];
    const float* W2     = (const float*)d_in[8];
    const float* g2     = (const float*)d_in[9];
    const float* b2     = (const float*)d_in[10];
    const float* m2     = (const float*)d_in[11];
    const float* v2     = (const float*)d_in[12];
    const int*   bsz    = (const int*)d_in[13];

    int n = in_sizes[0] / CIN;
    int m = in_sizes[2] / 4;

    fill_grid_kernel<<<(GRID_SZ / 4 + 255) / 256, 256>>>();
    scatter_kernel<<<(n + 255) / 256, 256>>>(coors, n);

    int smem1 = 27 * C1 * 32 * (int)sizeof(float);   // 110,592 B
    cudaFuncSetAttribute(conv1_kernel, cudaFuncAttributeMaxDynamicSharedMemorySize, smem1);
    conv1_kernel<<<(n + 255) / 256, 512, smem1>>>(feat, coors, W1, g1, b1, m1, v1, n);

    int smem2 = 27 * 32 * 32 * (int)sizeof(float);   // 110,592 B (half of W2)
    cudaFuncSetAttribute(conv2_kernel, cudaFuncAttributeMaxDynamicSharedMemorySize, smem2);
    int rowblocks = (m + 255) / 256;
    conv2_kernel<<<rowblocks * 2, 512, smem2>>>(ocoors, W2, g2, b2, m2, v2,
                                                (float*)d_out, m);

    int tail = out_size - m * 64;
    if (tail > 0) {
        tail_kernel<<<(tail + 255) / 256, 256>>>(ocoors, bsz, (float*)d_out, m, out_size);
    }
}